// round 15
// baseline (speedup 1.0000x reference)
#include <cuda_runtime.h>
#include <cuda_fp16.h>
#include <cstdint>
#include <math.h>

// Problem constants (fixed by the dataset)
#define N_NODES 100000
#define IN_F    256
#define HD      256
#define NH      4
#define DH      64
#define NEG_SLOPE 0.2f

// ---------------- scratch (device globals; no allocation allowed) ----------
__device__ __half g_feat_h[(size_t)N_NODES * HD];    // 51.2 MB (gather copy)
__device__ float g_el[N_NODES * NH];
__device__ float g_er[N_NODES * NH];
__device__ __half g_W_h[HD * IN_F];

// ---------------- helpers ---------------------------------------------------
__device__ __forceinline__ uint32_t smem_u32(const void* p) {
    uint32_t a;
    asm("{ .reg .u64 t; cvta.to.shared.u64 t, %1; cvt.u32.u64 %0, t; }"
        : "=r"(a) : "l"(p));
    return a;
}

#define LDSM_X4(r, addr)                                                      \
    asm volatile("ldmatrix.sync.aligned.m8n8.x4.shared.b16 {%0,%1,%2,%3}, [%4];" \
        : "=r"((r)[0]), "=r"((r)[1]), "=r"((r)[2]), "=r"((r)[3]) : "r"(addr))

#define MMA_F16(d, a, b0, b1)                                                 \
    asm volatile("mma.sync.aligned.m16n8k16.row.col.f32.f16.f16.f32 "         \
        "{%0,%1,%2,%3}, {%4,%5,%6,%7}, {%8,%9}, {%0,%1,%2,%3};"               \
        : "+f"((d)[0]), "+f"((d)[1]), "+f"((d)[2]), "+f"((d)[3])              \
        : "r"((a)[0]), "r"((a)[1]), "r"((a)[2]), "r"((a)[3]),                 \
          "r"(b0), "r"(b1))

#define CP_ASYNC16(saddr, gptr, sz)                                           \
    asm volatile("cp.async.cg.shared.global [%0], [%1], 16, %2;"              \
        :: "r"(saddr), "l"(gptr), "r"(sz))

// Streaming store (evict-first) so `out` does not evict feat_h from L2
__device__ __forceinline__ void stg_cs4(float* p, float a, float b, float c, float d) {
    asm volatile("st.global.cs.v4.f32 [%0], {%1,%2,%3,%4};"
                 :: "l"(p), "f"(a), "f"(b), "f"(c), "f"(d));
}

// ---------------- Kernel A: fp32 -> fp16 (W only, tiny) --------------------
__global__ void convert_kernel(const float* __restrict__ src,
                               __half* __restrict__ dst, int n4)
{
    int i = blockIdx.x * blockDim.x + threadIdx.x;
    if (i >= n4) return;
    float4 v = reinterpret_cast<const float4*>(src)[i];
    __half2* hp = reinterpret_cast<__half2*>(dst);
    hp[2 * i]     = __floats2half2_rn(v.x, v.y);
    hp[2 * i + 1] = __floats2half2_rn(v.z, v.w);
}

// ---------------- Kernel B: fp16 HMMA GEMM + fused el/er -------------------
// C[128,256] per CTA (full N) so A is read from DRAM exactly once.
// 512 threads, 16 warps, warp tile 32x64 (one head per warp).
// smem per stage: A 128x32 fp16 (80B rows) 10240 | W 256x32 fp16 20480.
#define STAGE_BYTES 30720
#define ROWB 80

__global__ __launch_bounds__(512, 1)
void gemm_hmma_kernel(const float* __restrict__ A,
                      const float* __restrict__ attn_l,
                      const float* __restrict__ attn_r, int M)
{
    extern __shared__ char smem[];
    const uint32_t sbase = smem_u32(smem);
    const int tid  = threadIdx.x;
    const int lane = tid & 31;
    const int wid  = tid >> 5;
    const int row0 = blockIdx.x * 128;
    const int wm   = (wid >> 2) * 32;   // warp m offset (0..96)
    const int wn   = (wid & 3) * 64;    // warp n offset = head * 64

    float acc[2][8][4];
    #pragma unroll
    for (int mt = 0; mt < 2; mt++)
        #pragma unroll
        for (int nt = 0; nt < 8; nt++)
            #pragma unroll
            for (int r = 0; r < 4; r++) acc[mt][nt][r] = 0.f;

    // W stage loader: 256 rows x 4 segs = 1024 16B chunks / 512 thr = 2 each
    auto load_W = [&](int chunk, int stage) {
        #pragma unroll
        for (int j = 0; j < 2; j++) {
            int t   = tid + j * 512;
            int row = t >> 2;
            int seg = t & 3;
            const __half* gp = g_W_h
                + (size_t)row * IN_F + chunk * 32 + seg * 8;
            uint32_t sa = sbase + stage * STAGE_BYTES + 10240
                        + row * ROWB + seg * 16;
            CP_ASYNC16(sa, gp, 16);
        }
        asm volatile("cp.async.commit_group;");
    };

    // A chunk: 128 rows x 32 fp32 = 1024 float4 / 512 thr = 2 each
    float4 areg[2];
    auto ldg_A = [&](int chunk) {
        #pragma unroll
        for (int j = 0; j < 2; j++) {
            int idx = tid + j * 512;
            int row = idx >> 3;
            int seg = idx & 7;
            int gr  = row0 + row;
            areg[j] = (gr < M)
                ? *reinterpret_cast<const float4*>(
                      A + (size_t)gr * IN_F + chunk * 32 + seg * 4)
                : make_float4(0.f, 0.f, 0.f, 0.f);
        }
    };
    auto sts_A = [&](int stage) {
        #pragma unroll
        for (int j = 0; j < 2; j++) {
            int idx = tid + j * 512;
            int row = idx >> 3;
            int seg = idx & 7;
            float4 v = areg[j];
            __half2 lo2 = __floats2half2_rn(v.x, v.y);
            __half2 hi2 = __floats2half2_rn(v.z, v.w);
            char* base = smem + stage * STAGE_BYTES + row * ROWB + seg * 8;
            *reinterpret_cast<__half2*>(base)     = lo2;
            *reinterpret_cast<__half2*>(base + 4) = hi2;
        }
    };

    auto compute = [&](int stage) {
        const uint32_t sb = sbase + stage * STAGE_BYTES;
        #pragma unroll
        for (int ks = 0; ks < 2; ks++) {
            const int k0 = ks * 16;
            uint32_t af[2][4], bh[4][4];
            #pragma unroll
            for (int mt = 0; mt < 2; mt++) {
                int r = wm + mt * 16 + (lane & 15);
                int c = k0 + ((lane >> 4) << 3);
                LDSM_X4(af[mt], sb + r * ROWB + c * 2);
            }
            #pragma unroll
            for (int p = 0; p < 4; p++) {
                int matid = lane >> 3;
                int nr = wn + p * 16 + ((matid >> 1) << 3) + (lane & 7);
                int kc = k0 + ((matid & 1) << 3);
                LDSM_X4(bh[p], sb + 10240 + nr * ROWB + kc * 2);
            }
            #pragma unroll
            for (int mt = 0; mt < 2; mt++) {
                #pragma unroll
                for (int nt = 0; nt < 8; nt++) {
                    uint32_t b0 = bh[nt >> 1][(nt & 1) * 2];
                    uint32_t b1 = bh[nt >> 1][(nt & 1) * 2 + 1];
                    MMA_F16(acc[mt][nt], af[mt], b0, b1);
                }
            }
        }
    };

    ldg_A(0);
    load_W(0, 0);
    #pragma unroll 1
    for (int ch = 0; ch < 8; ch++) {
        const int s = ch & 1;
        if (ch < 7) {
            load_W(ch + 1, s ^ 1);
            asm volatile("cp.async.wait_group 1;");
        } else {
            asm volatile("cp.async.wait_group 0;");
        }
        sts_A(s);
        __syncthreads();
        if (ch < 7) ldg_A(ch + 1);
        compute(s);
        __syncthreads();
    }

    // ---- epilogue 1: fp16 stores to g_feat_h -------------------------------
    #pragma unroll
    for (int mt = 0; mt < 2; mt++) {
        int m = row0 + wm + mt * 16 + (lane >> 2);
        #pragma unroll
        for (int nt = 0; nt < 8; nt++) {
            int n = wn + nt * 8 + (lane & 3) * 2;
            if (m < M) {
                __half2 v = __floats2half2_rn(acc[mt][nt][0], acc[mt][nt][1]);
                *reinterpret_cast<__half2*>(g_feat_h + (size_t)m * HD + n) = v;
            }
            if (m + 8 < M) {
                __half2 v = __floats2half2_rn(acc[mt][nt][2], acc[mt][nt][3]);
                *reinterpret_cast<__half2*>(g_feat_h + (size_t)(m + 8) * HD + n) = v;
            }
        }
    }

    // ---- epilogue 2: fused el/er — warp's 64 cols == one full head ---------
    {
        const int h = wid & 3;
        float el0 = 0.f, er0 = 0.f, el1 = 0.f, er1 = 0.f;
        #pragma unroll
        for (int nt = 0; nt < 8; nt++) {
            int c = wn + nt * 8 + (lane & 3) * 2;
            float al0 = __ldg(attn_l + c), al1 = __ldg(attn_l + c + 1);
            float ar0 = __ldg(attn_r + c), ar1 = __ldg(attn_r + c + 1);
            // mt = 0 rows
            el0 = fmaf(acc[0][nt][0], al0, fmaf(acc[0][nt][1], al1, el0));
            er0 = fmaf(acc[0][nt][0], ar0, fmaf(acc[0][nt][1], ar1, er0));
            el1 = fmaf(acc[0][nt][2], al0, fmaf(acc[0][nt][3], al1, el1));
            er1 = fmaf(acc[0][nt][2], ar0, fmaf(acc[0][nt][3], ar1, er1));
        }
        float el2 = 0.f, er2 = 0.f, el3 = 0.f, er3 = 0.f;
        #pragma unroll
        for (int nt = 0; nt < 8; nt++) {
            int c = wn + nt * 8 + (lane & 3) * 2;
            float al0 = __ldg(attn_l + c), al1 = __ldg(attn_l + c + 1);
            float ar0 = __ldg(attn_r + c), ar1 = __ldg(attn_r + c + 1);
            // mt = 1 rows
            el2 = fmaf(acc[1][nt][0], al0, fmaf(acc[1][nt][1], al1, el2));
            er2 = fmaf(acc[1][nt][0], ar0, fmaf(acc[1][nt][1], ar1, er2));
            el3 = fmaf(acc[1][nt][2], al0, fmaf(acc[1][nt][3], al1, el3));
            er3 = fmaf(acc[1][nt][2], ar0, fmaf(acc[1][nt][3], ar1, er3));
        }
        #pragma unroll
        for (int o = 1; o < 4; o <<= 1) {
            el0 += __shfl_xor_sync(0xffffffffu, el0, o);
            er0 += __shfl_xor_sync(0xffffffffu, er0, o);
            el1 += __shfl_xor_sync(0xffffffffu, el1, o);
            er1 += __shfl_xor_sync(0xffffffffu, er1, o);
            el2 += __shfl_xor_sync(0xffffffffu, el2, o);
            er2 += __shfl_xor_sync(0xffffffffu, er2, o);
            el3 += __shfl_xor_sync(0xffffffffu, el3, o);
            er3 += __shfl_xor_sync(0xffffffffu, er3, o);
        }
        if ((lane & 3) == 0) {
            int m0 = row0 + wm + (lane >> 2);          // mt 0
            int m1 = row0 + wm + 16 + (lane >> 2);     // mt 1
            if (m0 < M)     { g_el[m0 * NH + h] = el0;       g_er[m0 * NH + h] = er0; }
            if (m0 + 8 < M) { g_el[(m0 + 8) * NH + h] = el1; g_er[(m0 + 8) * NH + h] = er1; }
            if (m1 < M)     { g_el[m1 * NH + h] = el2;       g_er[m1 * NH + h] = er2; }
            if (m1 + 8 < M) { g_el[(m1 + 8) * NH + h] = el3; g_er[(m1 + 8) * NH + h] = er3; }
        }
    }
}

// ---------------- Kernel C: edge softmax + SpMM (warp per node) ------------
__global__ __launch_bounds__(256)
void agg_kernel(const int* __restrict__ row_ptr,
                const int* __restrict__ col_ind,
                float* __restrict__ out, int M)
{
    __shared__ float s_a[8][32][4];
    __shared__ int   s_src[8][32];
    const int w    = threadIdx.x >> 5;
    const int lane = threadIdx.x & 31;
    const int n    = blockIdx.x * 8 + w;
    if (n >= M) return;

    const int lo  = row_ptr[n];
    const int deg = row_ptr[n + 1] - lo;
    float* op = out + (size_t)n * HD + lane * 8;

    if (deg <= 0) {
        stg_cs4(op,     0.f, 0.f, 0.f, 0.f);
        stg_cs4(op + 4, 0.f, 0.f, 0.f, 0.f);
        return;
    }

    // ---- edge softmax (lane = edge index) ----------------------------------
    int src = 0;
    float4 e4 = make_float4(-INFINITY, -INFINITY, -INFINITY, -INFINITY);
    float4 el4 = *reinterpret_cast<const float4*>(g_el + n * NH);
    if (lane < deg) {
        src = col_ind[lo + lane];
        float4 er4 = *reinterpret_cast<const float4*>(g_er + src * NH);
        float x;
        x = er4.x + el4.x; e4.x = (x > 0.f) ? x : NEG_SLOPE * x;
        x = er4.y + el4.y; e4.y = (x > 0.f) ? x : NEG_SLOPE * x;
        x = er4.z + el4.z; e4.z = (x > 0.f) ? x : NEG_SLOPE * x;
        x = er4.w + el4.w; e4.w = (x > 0.f) ? x : NEG_SLOPE * x;
    }
    float4 mx = e4;
    #pragma unroll
    for (int o = 16; o; o >>= 1) {
        mx.x = fmaxf(mx.x, __shfl_xor_sync(0xffffffffu, mx.x, o));
        mx.y = fmaxf(mx.y, __shfl_xor_sync(0xffffffffu, mx.y, o));
        mx.z = fmaxf(mx.z, __shfl_xor_sync(0xffffffffu, mx.z, o));
        mx.w = fmaxf(mx.w, __shfl_xor_sync(0xffffffffu, mx.w, o));
    }
    float4 p = make_float4(0.f, 0.f, 0.f, 0.f);
    if (lane < deg) {
        p.x = __expf(e4.x - mx.x);
        p.y = __expf(e4.y - mx.y);
        p.z = __expf(e4.z - mx.z);
        p.w = __expf(e4.w - mx.w);
    }
    float4 s = p;
    #pragma unroll
    for (int o = 16; o; o >>= 1) {
        s.x += __shfl_xor_sync(0xffffffffu, s.x, o);
        s.y += __shfl_xor_sync(0xffffffffu, s.y, o);
        s.z += __shfl_xor_sync(0xffffffffu, s.z, o);
        s.w += __shfl_xor_sync(0xffffffffu, s.w, o);
    }
    p.x /= s.x; p.y /= s.y; p.z /= s.z; p.w /= s.w;
    if (lane < deg) {
        *reinterpret_cast<float4*>(&s_a[w][lane][0]) = p;
        s_src[w][lane] = src;
    }
    __syncwarp();

    // ---- SpMM: lane covers cols [lane*8, +8); head = lane>>3 ---------------
    const int hsel = lane >> 3;
    const __half* base = g_feat_h + lane * 8;
    float acc[8];
    #pragma unroll
    for (int i = 0; i < 8; i++) acc[i] = 0.f;

    if (deg == 16) {
        #pragma unroll
        for (int j = 0; j < 16; j++) {
            int   sj = s_src[w][j];
            float a  = s_a[w][j][hsel];
            uint4 q = __ldg(reinterpret_cast<const uint4*>(base + (size_t)sj * HD));
            float2 f0 = __half22float2(*reinterpret_cast<__half2*>(&q.x));
            float2 f1 = __half22float2(*reinterpret_cast<__half2*>(&q.y));
            float2 f2 = __half22float2(*reinterpret_cast<__half2*>(&q.z));
            float2 f3 = __half22float2(*reinterpret_cast<__half2*>(&q.w));
            acc[0] = fmaf(a, f0.x, acc[0]);
            acc[1] = fmaf(a, f0.y, acc[1]);
            acc[2] = fmaf(a, f1.x, acc[2]);
            acc[3] = fmaf(a, f1.y, acc[3]);
            acc[4] = fmaf(a, f2.x, acc[4]);
            acc[5] = fmaf(a, f2.y, acc[5]);
            acc[6] = fmaf(a, f3.x, acc[6]);
            acc[7] = fmaf(a, f3.y, acc[7]);
        }
    } else {
        #pragma unroll 4
        for (int j = 0; j < deg; j++) {
            int   sj = s_src[w][j];
            float a  = s_a[w][j][hsel];
            uint4 q = __ldg(reinterpret_cast<const uint4*>(base + (size_t)sj * HD));
            float2 f0 = __half22float2(*reinterpret_cast<__half2*>(&q.x));
            float2 f1 = __half22float2(*reinterpret_cast<__half2*>(&q.y));
            float2 f2 = __half22float2(*reinterpret_cast<__half2*>(&q.z));
            float2 f3 = __half22float2(*reinterpret_cast<__half2*>(&q.w));
            acc[0] = fmaf(a, f0.x, acc[0]);
            acc[1] = fmaf(a, f0.y, acc[1]);
            acc[2] = fmaf(a, f1.x, acc[2]);
            acc[3] = fmaf(a, f1.y, acc[3]);
            acc[4] = fmaf(a, f2.x, acc[4]);
            acc[5] = fmaf(a, f2.y, acc[5]);
            acc[6] = fmaf(a, f3.x, acc[6]);
            acc[7] = fmaf(a, f3.y, acc[7]);
        }
    }
    stg_cs4(op,     acc[0], acc[1], acc[2], acc[3]);
    stg_cs4(op + 4, acc[4], acc[5], acc[6], acc[7]);
}

// ---------------- launch ---------------------------------------------------
extern "C" void kernel_launch(void* const* d_in, const int* in_sizes, int n_in,
                              void* d_out, int out_size)
{
    const int*   row_ptr = (const int*)  d_in[0];
    const int*   col_ind = (const int*)  d_in[1];
    const float* feat    = (const float*)d_in[2];
    const float* W       = (const float*)d_in[3];
    const float* attn_l  = (const float*)d_in[4];
    const float* attn_r  = (const float*)d_in[5];
    float* out = (float*)d_out;

    int M = in_sizes[0] - 1;   // number of nodes

    void *w_h;
    cudaGetSymbolAddress(&w_h, g_W_h);

    // 1) fp16 convert of W
    {
        int w4 = in_sizes[3] / 4;
        convert_kernel<<<(w4 + 255) / 256, 256>>>(W, (__half*)w_h, w4);
    }

    // 2) fp16 HMMA GEMM (full-N tile, A read once) + fused el/er, fp16 out
    {
        static int smem_set = 0;
        if (!smem_set) {
            cudaFuncSetAttribute(gemm_hmma_kernel,
                                 cudaFuncAttributeMaxDynamicSharedMemorySize,
                                 2 * STAGE_BYTES);
            smem_set = 1;
        }
        int blocks = (M + 127) / 128;
        gemm_hmma_kernel<<<blocks, 512, 2 * STAGE_BYTES>>>(feat, attn_l, attn_r, M);
    }

    // 3) edge softmax + aggregate (warp per node, fp16 gather)
    {
        int blocks = (M + 7) / 8;
        agg_kernel<<<blocks, 256>>>(row_ptr, col_ind, out, M);
    }
}